// round 14
// baseline (speedup 1.0000x reference)
#include <cuda_runtime.h>
#include <cstdint>

// SubsampledRelativeAttention (closed form, validated R1-R13):
//   h = b % 8, c = t >> 2, E = [e1 ; e2[1:]] (511 rows)
//   out[b,t,s] = q[b,t] . E[h, j],  j = 255 - c + s
// mma.sync m16n8k8 TF32 banded GEMM.
// R14: R13 with PAIRED j-frag accumulation -> 4 independent HMMA chains
// (2 mt x 2 nt, 16 acc regs) to cut acc-RAW dependency stalls.

#define TT 1024
#define SS 256
#define DD 64

constexpr int TM   = 128;     // t rows per CTA (4 warps x 32 rows)
constexpr int JC   = 64;      // E rows per chunk
constexpr int NCH  = 5;       // 5*64 = 320 >= 287 band width (c spans 32)
constexpr int STRE = 68;      // Es/Qs stride (words): frag LDS conflict-free
constexpr int STRS = 72;      // St stride (words): STS.64 conflict-free
constexpr int SMEM_BYTES = TM * STRS * 4 + JC * STRE * 4;   // 54272

__device__ __forceinline__ uint32_t f2tf32(float x) {
    uint32_t r;
    asm("cvt.rna.tf32.f32 %0, %1;" : "=r"(r) : "f"(x));
    return r;
}
__device__ __forceinline__ uint32_t smem_u32(const void* p) {
    uint32_t a;
    asm("{ .reg .u64 t; cvta.to.shared.u64 t, %1; cvt.u32.u64 %0, t; }"
        : "=r"(a) : "l"(p));
    return a;
}
__device__ __forceinline__ void cp_async16(uint32_t dst, const void* src) {
    asm volatile("cp.async.cg.shared.global [%0], [%1], 16;"
                 :: "r"(dst), "l"(src));
}
__device__ __forceinline__ void cp_commit() {
    asm volatile("cp.async.commit_group;" ::: "memory");
}
__device__ __forceinline__ void cp_wait0() {
    asm volatile("cp.async.wait_group 0;" ::: "memory");
}

__global__ __launch_bounds__(128, 4)
void srel_tf32_kernel(const float* __restrict__ q,
                      const float* __restrict__ e1,
                      const float* __restrict__ e2,
                      float* __restrict__ out)
{
    extern __shared__ __align__(16) uint32_t smem[];
    uint32_t* Qs = smem;                                   // [128][68] (init only)
    float*    St = reinterpret_cast<float*>(smem);         // [128][72] aliases Qs
    uint32_t* Es = smem + TM * STRS;                       // [64][68] raw f32 bits

    const int blk  = blockIdx.x;
    const int b    = blk >> 3;            // 8 t-tiles per batch row
    const int t0   = (blk & 7) * TM;
    const int h    = b & 7;
    const int c0   = t0 >> 2;
    const int jbase = 224 - c0;           // min j over tile (c spans c0..c0+31)

    const int tid  = threadIdx.x;
    const int wid  = tid >> 5;            // warp owns rows [wid*32, +32)
    const int lane = tid & 31;
    const int r    = lane >> 2;
    const int cidx = lane & 3;

    // warp frag window: rows span c-c0 in [8w,8w+7] -> j_off [24-8w, 286-8w]
    const int glo = (24 - 8 * wid) >> 3;    // 3,2,1,0
    const int ghi = (286 - 8 * wid) >> 3;   // 35,34,33,32

    const float4* e1h = reinterpret_cast<const float4*>(e1 + (size_t)h * SS * DD);
    const float4* e2h = reinterpret_cast<const float4*>(e2 + (size_t)h * SS * DD);
    const uint32_t es_base = smem_u32(Es);

    // ---- prefetch E chunk 0 (8 back-to-back LDGSTS) ----
    {
        const int jc = jbase;
        #pragma unroll
        for (int u = 0; u < 8; u++) {
            const int i = tid + u * 128;
            const int row = i >> 4, c16 = i & 15;
            const int j = jc + row;
            const float4* src;
            if (j <= 255) {
                src = e1h + j * 16 + c16;            // E rows [0,255] = e1
            } else {
                int j2 = j - 255;                    // E rows [256,510] = e2[1:]
                if (j2 > 255) j2 = 255;              // overrun rows never flushed
                src = e2h + j2 * 16 + c16;
            }
            cp_async16(es_base + (row * STRE + c16 * 4) * 4, src);
        }
        cp_commit();
    }

    // ---- Q tile (128 x 64) -> smem tf32 ----
    const float4* qb4 = reinterpret_cast<const float4*>(
                            q + ((size_t)b * TT + t0) * DD);
    for (int i = tid; i < TM * DD / 4; i += 128) {
        const int row = i >> 4;
        const int k4  = (i & 15) << 2;
        const float4 v = qb4[i];
        uint4 u;
        u.x = f2tf32(v.x); u.y = f2tf32(v.y);
        u.z = f2tf32(v.z); u.w = f2tf32(v.w);
        *reinterpret_cast<uint4*>(Qs + row * STRE + k4) = u;
    }
    __syncthreads();

    // ---- extract A fragments once: 2 m-frags (rows wid*32 + mt*16 + ..) ----
    uint32_t ah[8][2][4];
    #pragma unroll
    for (int mt = 0; mt < 2; mt++) {
        const uint32_t* Aq = Qs + (wid * 32 + mt * 16 + r) * STRE + cidx;
        #pragma unroll
        for (int ks = 0; ks < 8; ks++) {
            const int k0 = ks * 8;
            ah[ks][mt][0] = Aq[k0];
            ah[ks][mt][1] = Aq[8 * STRE + k0];
            ah[ks][mt][2] = Aq[k0 + 4];
            ah[ks][mt][3] = Aq[8 * STRE + k0 + 4];
        }
    }
    cp_wait0();
    __syncthreads();   // extraction done -> Qs region free for St; Es ready

    const uint32_t* Be = Es + r * STRE + cidx;

    // flush invariants: row0 = wid*32; s(i) = jc + ((t0+row0+i)>>2) - 255 + lane
    const int    row0   = wid * 32;
    const int    sb0    = jbase + ((t0 + row0) >> 2) - 255 + lane;  // ch=0, i=0
    float*       ogbase = out + ((size_t)b * TT + t0 + row0) * SS;
    const float* stbase = St + row0 * STRS;

    for (int ch = 0; ch < NCH; ch++) {
        // ---- paired-frag MMA + stage: 4 independent HMMA chains ----
        #pragma unroll
        for (int pp = 0; pp < 4; pp++) {
            const int g0  = ch * 8 + 2 * pp;
            const int g1  = g0 + 1;
            const bool in0 = (g0 >= glo) && (g0 <= ghi);
            const bool in1 = (g1 >= glo) && (g1 <= ghi);
            if (!in0 && !in1) continue;          // warp-uniform skip

            float acc[2][2][4];                  // [nt-in-pair][mt][4]
            #pragma unroll
            for (int n2 = 0; n2 < 2; n2++)
                #pragma unroll
                for (int mt = 0; mt < 2; mt++)
                    #pragma unroll
                    for (int v = 0; v < 4; v++)
                        acc[n2][mt][v] = 0.0f;

            const uint32_t* p0 = Be + (2 * pp) * 8 * STRE;
            const uint32_t* p1 = p0 + 8 * STRE;
            #pragma unroll
            for (int ks = 0; ks < 8; ks++) {
                const uint32_t b00 = p0[ks * 8];      // raw f32 = tf32 truncation
                const uint32_t b01 = p0[ks * 8 + 4];
                const uint32_t b10 = p1[ks * 8];
                const uint32_t b11 = p1[ks * 8 + 4];
                #pragma unroll
                for (int mt = 0; mt < 2; mt++) {
                    asm volatile(
                        "mma.sync.aligned.m16n8k8.row.col.f32.tf32.tf32.f32 "
                        "{%0,%1,%2,%3}, {%4,%5,%6,%7}, {%8,%9}, {%0,%1,%2,%3};"
                        : "+f"(acc[0][mt][0]), "+f"(acc[0][mt][1]),
                          "+f"(acc[0][mt][2]), "+f"(acc[0][mt][3])
                        : "r"(ah[ks][mt][0]), "r"(ah[ks][mt][1]),
                          "r"(ah[ks][mt][2]), "r"(ah[ks][mt][3]),
                          "r"(b00), "r"(b01));
                    asm volatile(
                        "mma.sync.aligned.m16n8k8.row.col.f32.tf32.tf32.f32 "
                        "{%0,%1,%2,%3}, {%4,%5,%6,%7}, {%8,%9}, {%0,%1,%2,%3};"
                        : "+f"(acc[1][mt][0]), "+f"(acc[1][mt][1]),
                          "+f"(acc[1][mt][2]), "+f"(acc[1][mt][3])
                        : "r"(ah[ks][mt][0]), "r"(ah[ks][mt][1]),
                          "r"(ah[ks][mt][2]), "r"(ah[ks][mt][3]),
                          "r"(b10), "r"(b11));
                }
            }

            // stage in-window frags (warp-private St rows, STS.64)
            #pragma unroll
            for (int n2 = 0; n2 < 2; n2++) {
                if (n2 == 0 ? !in0 : !in1) continue;
                const int nt = 2 * pp + n2;
                #pragma unroll
                for (int mt = 0; mt < 2; mt++) {
                    #pragma unroll
                    for (int half = 0; half < 2; half++) {
                        const int row = row0 + mt * 16 + half * 8 + r;
                        float2 v;
                        v.x = acc[n2][mt][half * 2 + 0];
                        v.y = acc[n2][mt][half * 2 + 1];
                        *reinterpret_cast<float2*>(
                            St + row * STRS + nt * 8 + 2 * cidx) = v;
                    }
                }
            }
        }

        __syncthreads();   // all warps done reading Es; stages visible

        // ---- issue next E prefetch (latency hidden by flush) ----
        if (ch < NCH - 1) {
            const int jcn = jbase + (ch + 1) * JC;
            #pragma unroll
            for (int u = 0; u < 8; u++) {
                const int i = tid + u * 128;
                const int row = i >> 4, c16 = i & 15;
                const int j = jcn + row;
                const float4* src;
                if (j <= 255) {
                    src = e1h + j * 16 + c16;
                } else {
                    int j2 = j - 255;
                    if (j2 > 255) j2 = 255;
                    src = e2h + j2 * 16 + c16;
                }
                cp_async16(es_base + (row * STRE + c16 * 4) * 4, src);
            }
            cp_commit();
        }

        // ---- warp-private coalesced flush: 32 rows, pointer-stepped ----
        {
            int s0 = sb0 + ch * JC;         // s grows by +1 every 4 rows
            const float* st = stbase;
            float* og = ogbase;
            #pragma unroll
            for (int i = 0; i < 32; i++) {
                const float v0 = st[lane];
                const float v1 = st[32 + lane];
                if ((unsigned)s0 < (unsigned)SS)        og[s0]      = v0;
                if ((unsigned)(s0 + 32) < (unsigned)SS) og[s0 + 32] = v1;
                st += STRS;
                og += SS;
                if ((i & 3) == 3) s0 += 1;
            }
        }

        if (ch < NCH - 1) {
            cp_wait0();
            __syncthreads();   // next Es visible
        }
    }
}

extern "C" void kernel_launch(void* const* d_in, const int* in_sizes, int n_in,
                              void* d_out, int out_size)
{
    const float* q  = (const float*)d_in[0];
    const float* e1 = (const float*)d_in[1];
    const float* e2 = (const float*)d_in[2];
    float* out      = (float*)d_out;

    cudaFuncSetAttribute(srel_tf32_kernel,
                         cudaFuncAttributeMaxDynamicSharedMemorySize, SMEM_BYTES);
    srel_tf32_kernel<<<128 * (TT / TM), 128, SMEM_BYTES>>>(q, e1, e2, out);
}

// round 15
// speedup vs baseline: 1.0697x; 1.0697x over previous
#include <cuda_runtime.h>
#include <cstdint>

// SubsampledRelativeAttention (closed form, validated R1-R14):
//   h = b % 8, c = t >> 2, E = [e1 ; e2[1:]] (511 rows)
//   out[b,t,s] = q[b,t] . E[h, j],  j = 255 - c + s
// mma.sync m16n8k8 TF32 banded GEMM.
// R15: R13 base + pair-per-lane flush (LDS.64, STG.64 on even-srow rows)
// + warp-uniform interior fast path (no bound predicates mid-band).

#define TT 1024
#define SS 256
#define DD 64

constexpr int TM   = 128;     // t rows per CTA (4 warps x 32 rows)
constexpr int JC   = 64;      // E rows per chunk
constexpr int NCH  = 5;       // 5*64 = 320 >= 287 band width (c spans 32)
constexpr int STRE = 68;      // Es/Qs stride (words): frag LDS conflict-free
constexpr int STRS = 72;      // St stride (words): STS.64 conflict-free
constexpr int SMEM_BYTES = TM * STRS * 4 + JC * STRE * 4;   // 54272

__device__ __forceinline__ uint32_t f2tf32(float x) {
    uint32_t r;
    asm("cvt.rna.tf32.f32 %0, %1;" : "=r"(r) : "f"(x));
    return r;
}
__device__ __forceinline__ uint32_t smem_u32(const void* p) {
    uint32_t a;
    asm("{ .reg .u64 t; cvta.to.shared.u64 t, %1; cvt.u32.u64 %0, t; }"
        : "=r"(a) : "l"(p));
    return a;
}
__device__ __forceinline__ void cp_async16(uint32_t dst, const void* src) {
    asm volatile("cp.async.cg.shared.global [%0], [%1], 16;"
                 :: "r"(dst), "l"(src));
}
__device__ __forceinline__ void cp_commit() {
    asm volatile("cp.async.commit_group;" ::: "memory");
}
__device__ __forceinline__ void cp_wait0() {
    asm volatile("cp.async.wait_group 0;" ::: "memory");
}

__global__ __launch_bounds__(128, 4)
void srel_tf32_kernel(const float* __restrict__ q,
                      const float* __restrict__ e1,
                      const float* __restrict__ e2,
                      float* __restrict__ out)
{
    extern __shared__ __align__(16) uint32_t smem[];
    uint32_t* Qs = smem;                                   // [128][68] (init only)
    float*    St = reinterpret_cast<float*>(smem);         // [128][72] aliases Qs
    uint32_t* Es = smem + TM * STRS;                       // [64][68] raw f32 bits

    const int blk  = blockIdx.x;
    const int b    = blk >> 3;            // 8 t-tiles per batch row
    const int t0   = (blk & 7) * TM;
    const int h    = b & 7;
    const int c0   = t0 >> 2;
    const int jbase = 224 - c0;           // min j over tile (c spans c0..c0+31)

    const int tid  = threadIdx.x;
    const int wid  = tid >> 5;            // warp owns rows [wid*32, +32)
    const int lane = tid & 31;
    const int r    = lane >> 2;
    const int cidx = lane & 3;

    // warp frag window: rows span c-c0 in [8w,8w+7] -> j_off [24-8w, 286-8w]
    const int glo = (24 - 8 * wid) >> 3;    // 3,2,1,0
    const int ghi = (286 - 8 * wid) >> 3;   // 35,34,33,32

    const float4* e1h = reinterpret_cast<const float4*>(e1 + (size_t)h * SS * DD);
    const float4* e2h = reinterpret_cast<const float4*>(e2 + (size_t)h * SS * DD);
    const uint32_t es_base = smem_u32(Es);

    // ---- prefetch E chunk 0 (8 back-to-back LDGSTS) ----
    {
        const int jc = jbase;
        #pragma unroll
        for (int u = 0; u < 8; u++) {
            const int i = tid + u * 128;
            const int row = i >> 4, c16 = i & 15;
            const int j = jc + row;
            const float4* src;
            if (j <= 255) {
                src = e1h + j * 16 + c16;            // E rows [0,255] = e1
            } else {
                int j2 = j - 255;                    // E rows [256,510] = e2[1:]
                if (j2 > 255) j2 = 255;              // overrun rows never flushed
                src = e2h + j2 * 16 + c16;
            }
            cp_async16(es_base + (row * STRE + c16 * 4) * 4, src);
        }
        cp_commit();
    }

    // ---- Q tile (128 x 64) -> smem tf32 ----
    const float4* qb4 = reinterpret_cast<const float4*>(
                            q + ((size_t)b * TT + t0) * DD);
    for (int i = tid; i < TM * DD / 4; i += 128) {
        const int row = i >> 4;
        const int k4  = (i & 15) << 2;
        const float4 v = qb4[i];
        uint4 u;
        u.x = f2tf32(v.x); u.y = f2tf32(v.y);
        u.z = f2tf32(v.z); u.w = f2tf32(v.w);
        *reinterpret_cast<uint4*>(Qs + row * STRE + k4) = u;
    }
    __syncthreads();

    // ---- extract A fragments once: 2 m-frags (rows wid*32 + mt*16 + ..) ----
    uint32_t ah[8][2][4];
    #pragma unroll
    for (int mt = 0; mt < 2; mt++) {
        const uint32_t* Aq = Qs + (wid * 32 + mt * 16 + r) * STRE + cidx;
        #pragma unroll
        for (int ks = 0; ks < 8; ks++) {
            const int k0 = ks * 8;
            ah[ks][mt][0] = Aq[k0];
            ah[ks][mt][1] = Aq[8 * STRE + k0];
            ah[ks][mt][2] = Aq[k0 + 4];
            ah[ks][mt][3] = Aq[8 * STRE + k0 + 4];
        }
    }
    cp_wait0();
    __syncthreads();   // extraction done -> Qs region free for St; Es ready

    const uint32_t* Be = Es + r * STRE + cidx;

    // flush invariants: row0 = wid*32
    const int    row0   = wid * 32;
    const int    sr0    = jbase + ((t0 + row0) >> 2) - 255;   // srow at ch=0,i=0
    float*       ogbase = out + ((size_t)b * TT + t0 + row0) * SS;
    const float* stbase = St + row0 * STRS;

    for (int ch = 0; ch < NCH; ch++) {
        // ---- frag-sequential MMA + stage: only 8 acc regs in flight ----
        #pragma unroll
        for (int nt = 0; nt < 8; nt++) {
            const int g = ch * 8 + nt;
            if (g < glo || g > ghi) continue;     // warp-uniform skip

            float acc[2][4];
            #pragma unroll
            for (int mt = 0; mt < 2; mt++)
                #pragma unroll
                for (int v = 0; v < 4; v++)
                    acc[mt][v] = 0.0f;

            const uint32_t* p = Be + nt * 8 * STRE;
            #pragma unroll
            for (int ks = 0; ks < 8; ks++) {
                const uint32_t b0 = p[ks * 8];        // raw f32 = tf32 truncation
                const uint32_t b1 = p[ks * 8 + 4];
                #pragma unroll
                for (int mt = 0; mt < 2; mt++)
                    asm volatile(
                        "mma.sync.aligned.m16n8k8.row.col.f32.tf32.tf32.f32 "
                        "{%0,%1,%2,%3}, {%4,%5,%6,%7}, {%8,%9}, {%0,%1,%2,%3};"
                        : "+f"(acc[mt][0]), "+f"(acc[mt][1]),
                          "+f"(acc[mt][2]), "+f"(acc[mt][3])
                        : "r"(ah[ks][mt][0]), "r"(ah[ks][mt][1]),
                          "r"(ah[ks][mt][2]), "r"(ah[ks][mt][3]),
                          "r"(b0), "r"(b1));
            }

            // stage this frag (warp-private St rows, STS.64 conflict-free)
            #pragma unroll
            for (int mt = 0; mt < 2; mt++) {
                #pragma unroll
                for (int half = 0; half < 2; half++) {
                    const int row = row0 + mt * 16 + half * 8 + r;
                    float2 v;
                    v.x = acc[mt][half * 2 + 0];
                    v.y = acc[mt][half * 2 + 1];
                    *reinterpret_cast<float2*>(St + row * STRS + nt * 8 + 2 * cidx) = v;
                }
            }
        }

        __syncthreads();   // all warps done reading Es; stages visible

        // ---- issue next E prefetch (latency hidden by flush) ----
        if (ch < NCH - 1) {
            const int jcn = jbase + (ch + 1) * JC;
            #pragma unroll
            for (int u = 0; u < 8; u++) {
                const int i = tid + u * 128;
                const int row = i >> 4, c16 = i & 15;
                const int j = jcn + row;
                const float4* src;
                if (j <= 255) {
                    src = e1h + j * 16 + c16;
                } else {
                    int j2 = j - 255;
                    if (j2 > 255) j2 = 255;
                    src = e2h + j2 * 16 + c16;
                }
                cp_async16(es_base + (row * STRE + c16 * 4) * 4, src);
            }
            cp_commit();
        }

        // ---- warp-private flush: lane owns s-pair (2*lane, 2*lane+1) ----
        {
            int srow = sr0 + ch * JC;       // row-window base; +1 every 4 rows
            const float* st = stbase;
            float* og = ogbase;
            if (srow >= 0 && srow <= 185) {
                // interior: every store in-range, no predicates
                #pragma unroll
                for (int i = 0; i < 32; i++) {
                    const float2 v = *reinterpret_cast<const float2*>(st + 2 * lane);
                    const int s0 = srow + 2 * lane;
                    if (srow & 1) {                 // row-uniform branch
                        og[s0]     = v.x;
                        og[s0 + 1] = v.y;
                    } else {
                        *reinterpret_cast<float2*>(og + s0) = v;   // STG.64
                    }
                    st += STRS;
                    og += SS;
                    if ((i & 3) == 3) srow += 1;
                }
            } else {
                // edge chunks: per-element predication
                #pragma unroll
                for (int i = 0; i < 32; i++) {
                    const float2 v = *reinterpret_cast<const float2*>(st + 2 * lane);
                    const int s0 = srow + 2 * lane;
                    if ((unsigned)s0 < (unsigned)SS)       og[s0]     = v.x;
                    if ((unsigned)(s0 + 1) < (unsigned)SS) og[s0 + 1] = v.y;
                    st += STRS;
                    og += SS;
                    if ((i & 3) == 3) srow += 1;
                }
            }
        }

        if (ch < NCH - 1) {
            cp_wait0();
            __syncthreads();   // next Es visible
        }
    }
}

extern "C" void kernel_launch(void* const* d_in, const int* in_sizes, int n_in,
                              void* d_out, int out_size)
{
    const float* q  = (const float*)d_in[0];
    const float* e1 = (const float*)d_in[1];
    const float* e2 = (const float*)d_in[2];
    float* out      = (float*)d_out;

    cudaFuncSetAttribute(srel_tf32_kernel,
                         cudaFuncAttributeMaxDynamicSharedMemorySize, SMEM_BYTES);
    srel_tf32_kernel<<<128 * (TT / TM), 128, SMEM_BYTES>>>(q, e1, e2, out);
}